// round 1
// baseline (speedup 1.0000x reference)
#include <cuda_runtime.h>
#include <math.h>

#define N_NODES 50000
#define N_EDGES 800000
#define D 128
#define H 256

// ---------------- device scratch (allocation-free rule: __device__ globals) ----------------
__device__ __align__(16) float g_n[(size_t)N_NODES * D];
__device__ __align__(16) float g_e[(size_t)N_EDGES * D];
__device__ __align__(16) float g_Ps[(size_t)N_NODES * H];
__device__ __align__(16) float g_Pr[(size_t)N_NODES * H];
__device__ __align__(16) float g_Pe[(size_t)N_EDGES * H];
__device__ __align__(16) float g_agg[(size_t)N_NODES * D];

__device__ __forceinline__ float gelu_tanh(float x) {
    const float c = 0.7978845608028654f;
    float t = tanhf(c * (x + 0.044715f * x * x * x));
    return 0.5f * x * (1.0f + t);
}

// =====================================================================================
// embed: out = LayerNorm(gelu(x @ W + b))   W: [128,128] row-major. 32 rows / CTA.
// smem: W (64KB) + xs (16KB) + ys (16KB) = 96KB
// =====================================================================================
__global__ __launch_bounds__(256, 1)
void embed_kernel(const float* __restrict__ x, const float* __restrict__ w,
                  const float* __restrict__ bias,
                  const float* __restrict__ lns, const float* __restrict__ lno,
                  float* __restrict__ out, int nrows)
{
    extern __shared__ float sm[];
    float* ws = sm;                 // 128*128
    float* xs = ws + 128 * 128;     // 32*128
    float* ys = xs + 32 * 128;      // 32*128
    const int tid = threadIdx.x;
    const int row0 = blockIdx.x * 32;

    for (int i = tid; i < 128 * 128 / 4; i += 256)
        ((float4*)ws)[i] = ((const float4*)w)[i];
    for (int i = tid; i < 32 * 128 / 4; i += 256) {
        int r = i >> 5;            // 32 float4 per row
        int row = row0 + r;
        float4 v = make_float4(0.f, 0.f, 0.f, 0.f);
        if (row < nrows) v = ((const float4*)x)[(size_t)row * 32 + (i & 31)];
        ((float4*)xs)[i] = v;
    }
    __syncthreads();

    const int tr = tid >> 5;   // rows tr*4..+4
    const int tc = tid & 31;   // cols tc*4..+4
    float acc[4][4];
#pragma unroll
    for (int i = 0; i < 4; i++)
#pragma unroll
        for (int j = 0; j < 4; j++) acc[i][j] = 0.f;

    for (int k = 0; k < 128; k += 4) {
        float4 a[4];
#pragma unroll
        for (int i = 0; i < 4; i++) a[i] = *(float4*)&xs[(tr * 4 + i) * 128 + k];
#pragma unroll
        for (int kk = 0; kk < 4; kk++) {
            float4 b = *(float4*)&ws[(k + kk) * 128 + tc * 4];
#pragma unroll
            for (int i = 0; i < 4; i++) {
                float av = ((float*)&a[i])[kk];
                acc[i][0] += av * b.x; acc[i][1] += av * b.y;
                acc[i][2] += av * b.z; acc[i][3] += av * b.w;
            }
        }
    }
    float4 bv = ((const float4*)bias)[tc];
#pragma unroll
    for (int i = 0; i < 4; i++) {
        int r = tr * 4 + i;
        ys[r * 128 + tc * 4 + 0] = gelu_tanh(acc[i][0] + bv.x);
        ys[r * 128 + tc * 4 + 1] = gelu_tanh(acc[i][1] + bv.y);
        ys[r * 128 + tc * 4 + 2] = gelu_tanh(acc[i][2] + bv.z);
        ys[r * 128 + tc * 4 + 3] = gelu_tanh(acc[i][3] + bv.w);
    }
    __syncthreads();

    const int wid = tid >> 5, lane = tid & 31;
    float4 sc = ((const float4*)lns)[lane];
    float4 of = ((const float4*)lno)[lane];
#pragma unroll
    for (int rr = 0; rr < 4; rr++) {
        int r = wid * 4 + rr;
        float4 v = ((float4*)ys)[r * 32 + lane];
        float s = v.x + v.y + v.z + v.w;
#pragma unroll
        for (int o = 16; o; o >>= 1) s += __shfl_xor_sync(0xffffffffu, s, o);
        float mean = s * (1.0f / 128.0f);
        float dx = v.x - mean, dy = v.y - mean, dz = v.z - mean, dw = v.w - mean;
        float q = dx * dx + dy * dy + dz * dz + dw * dw;
#pragma unroll
        for (int o = 16; o; o >>= 1) q += __shfl_xor_sync(0xffffffffu, q, o);
        float rstd = rsqrtf(q * (1.0f / 128.0f) + 1e-5f);
        int row = row0 + r;
        if (row < nrows) {
            float4 o4;
            o4.x = dx * rstd * sc.x + of.x;
            o4.y = dy * rstd * sc.y + of.y;
            o4.z = dz * rstd * sc.z + of.z;
            o4.w = dw * rstd * sc.w + of.w;
            ((float4*)out)[(size_t)row * 32 + lane] = o4;
        }
    }
}

// =====================================================================================
// gemm: C[M,256] = A[M,128] @ B[128,256].   64 rows / CTA, 8x8 microtile.
// smem: B (128KB) + A-tile (32KB) = 160KB
// =====================================================================================
__global__ __launch_bounds__(256, 1)
void gemm_k128_n256(const float* __restrict__ A, const float* __restrict__ B,
                    float* __restrict__ C, int M)
{
    extern __shared__ float sm[];
    float* Bs = sm;                 // 128*256
    float* As = Bs + 128 * 256;     // 64*128
    const int tid = threadIdx.x;
    const int row0 = blockIdx.x * 64;

    for (int i = tid; i < 128 * 256 / 4; i += 256)
        ((float4*)Bs)[i] = ((const float4*)B)[i];
    for (int i = tid; i < 64 * 128 / 4; i += 256) {
        int r = i >> 5;
        int row = row0 + r;
        float4 v = make_float4(0.f, 0.f, 0.f, 0.f);
        if (row < M) v = ((const float4*)A)[(size_t)row * 32 + (i & 31)];
        ((float4*)As)[i] = v;
    }
    __syncthreads();

    const int tr = tid >> 5;   // rows tr*8..+8
    const int tc = tid & 31;   // cols tc*8..+8
    float acc[8][8];
#pragma unroll
    for (int i = 0; i < 8; i++)
#pragma unroll
        for (int j = 0; j < 8; j++) acc[i][j] = 0.f;

    for (int k = 0; k < 128; k += 4) {
        float4 a[8];
#pragma unroll
        for (int i = 0; i < 8; i++) a[i] = *(float4*)&As[(tr * 8 + i) * 128 + k];
#pragma unroll
        for (int kk = 0; kk < 4; kk++) {
            float4 b0 = *(float4*)&Bs[(k + kk) * 256 + tc * 8];
            float4 b1 = *(float4*)&Bs[(k + kk) * 256 + tc * 8 + 4];
#pragma unroll
            for (int i = 0; i < 8; i++) {
                float av = ((float*)&a[i])[kk];
                acc[i][0] += av * b0.x; acc[i][1] += av * b0.y;
                acc[i][2] += av * b0.z; acc[i][3] += av * b0.w;
                acc[i][4] += av * b1.x; acc[i][5] += av * b1.y;
                acc[i][6] += av * b1.z; acc[i][7] += av * b1.w;
            }
        }
    }
#pragma unroll
    for (int i = 0; i < 8; i++) {
        int row = row0 + tr * 8 + i;
        if (row < M) {
            float4 o0 = make_float4(acc[i][0], acc[i][1], acc[i][2], acc[i][3]);
            float4 o1 = make_float4(acc[i][4], acc[i][5], acc[i][6], acc[i][7]);
            ((float4*)C)[(size_t)row * 64 + tc * 2 + 0] = o0;
            ((float4*)C)[(size_t)row * 64 + tc * 2 + 1] = o1;
        }
    }
}

// =====================================================================================
// edge_msg: m1 = relu(Ps[s]+Pr[r]+Pe+b1); m2 = relu(m1@W2+b2); agg[r] += m2
// 64 edges / CTA. smem: W2 (128KB) + m1 (64KB) + ridx = ~192.25KB
// =====================================================================================
__global__ __launch_bounds__(256, 1)
void edge_msg_kernel(const float* __restrict__ Ps, const float* __restrict__ Pr,
                     const float* __restrict__ Pe, const float* __restrict__ b1,
                     const float* __restrict__ w2, const float* __restrict__ b2,
                     const int* __restrict__ snd, const int* __restrict__ rcv,
                     float* __restrict__ agg, int E)
{
    extern __shared__ float sm[];
    float* w2s = sm;                 // 256*128
    float* m1  = w2s + 256 * 128;    // 64*256
    int* ridx  = (int*)(m1 + 64 * 256);
    const int tid = threadIdx.x;
    const int e0 = blockIdx.x * 64;

    for (int i = tid; i < 256 * 128 / 4; i += 256)
        ((float4*)w2s)[i] = ((const float4*)w2)[i];
    if (tid < 64) ridx[tid] = (e0 + tid < E) ? rcv[e0 + tid] : 0;

    for (int i = tid; i < 64 * 64; i += 256) {   // 64 edges x 64 float4
        int r = i >> 6;
        int c4 = i & 63;
        int eg = e0 + r;
        float4 v = make_float4(0.f, 0.f, 0.f, 0.f);
        if (eg < E) {
            int s = snd[eg];
            int rv = rcv[eg];
            float4 ps = ((const float4*)Ps)[(size_t)s * 64 + c4];
            float4 pr = ((const float4*)Pr)[(size_t)rv * 64 + c4];
            float4 pe = ((const float4*)Pe)[(size_t)eg * 64 + c4];
            float4 bb = ((const float4*)b1)[c4];
            v.x = fmaxf(ps.x + pr.x + pe.x + bb.x, 0.f);
            v.y = fmaxf(ps.y + pr.y + pe.y + bb.y, 0.f);
            v.z = fmaxf(ps.z + pr.z + pe.z + bb.z, 0.f);
            v.w = fmaxf(ps.w + pr.w + pe.w + bb.w, 0.f);
        }
        ((float4*)m1)[i] = v;
    }
    __syncthreads();

    const int tr = tid >> 5;   // rows tr*8..+8
    const int tc = tid & 31;   // cols tc*4..+4
    float acc[8][4];
#pragma unroll
    for (int i = 0; i < 8; i++)
#pragma unroll
        for (int j = 0; j < 4; j++) acc[i][j] = 0.f;

    for (int k = 0; k < 256; k += 4) {
        float4 a[8];
#pragma unroll
        for (int i = 0; i < 8; i++) a[i] = *(float4*)&m1[(tr * 8 + i) * 256 + k];
#pragma unroll
        for (int kk = 0; kk < 4; kk++) {
            float4 b = *(float4*)&w2s[(k + kk) * 128 + tc * 4];
#pragma unroll
            for (int i = 0; i < 8; i++) {
                float av = ((float*)&a[i])[kk];
                acc[i][0] += av * b.x; acc[i][1] += av * b.y;
                acc[i][2] += av * b.z; acc[i][3] += av * b.w;
            }
        }
    }
    float4 b2v = ((const float4*)b2)[tc];
#pragma unroll
    for (int i = 0; i < 8; i++) {
        int eg = e0 + tr * 8 + i;
        if (eg < E) {
            int rv = ridx[tr * 8 + i];
            float* dst = agg + (size_t)rv * 128 + tc * 4;
            atomicAdd(dst + 0, fmaxf(acc[i][0] + b2v.x, 0.f));
            atomicAdd(dst + 1, fmaxf(acc[i][1] + b2v.y, 0.f));
            atomicAdd(dst + 2, fmaxf(acc[i][2] + b2v.z, 0.f));
            atomicAdd(dst + 3, fmaxf(acc[i][3] + b2v.w, 0.f));
        }
    }
}

// =====================================================================================
// node_update: upd = LN(concat(n, agg) @ W + b); n_out = n + upd.  32 rows / CTA.
// smem: W (128KB) + xs (32KB) + ys (16KB) = 176KB
// =====================================================================================
__global__ __launch_bounds__(256, 1)
void node_update_kernel(const float* __restrict__ n_in, const float* __restrict__ agg,
                        const float* __restrict__ W, const float* __restrict__ bias,
                        const float* __restrict__ lns, const float* __restrict__ lno,
                        float* __restrict__ n_out, int N)
{
    extern __shared__ float sm[];
    float* Ws = sm;                 // 256*128
    float* xs = Ws + 256 * 128;     // 32*256
    float* ys = xs + 32 * 256;      // 32*128
    const int tid = threadIdx.x;
    const int row0 = blockIdx.x * 32;

    for (int i = tid; i < 256 * 128 / 4; i += 256)
        ((float4*)Ws)[i] = ((const float4*)W)[i];
    for (int i = tid; i < 32 * 64; i += 256) {   // 64 float4 per row
        int r = i >> 6, c4 = i & 63;
        int row = row0 + r;
        float4 v = make_float4(0.f, 0.f, 0.f, 0.f);
        if (row < N) {
            if (c4 < 32) v = ((const float4*)n_in)[(size_t)row * 32 + c4];
            else         v = ((const float4*)agg)[(size_t)row * 32 + (c4 - 32)];
        }
        ((float4*)xs)[i] = v;
    }
    __syncthreads();

    const int tr = tid >> 5;   // rows tr*4..+4
    const int tc = tid & 31;   // cols tc*4..+4
    float acc[4][4];
#pragma unroll
    for (int i = 0; i < 4; i++)
#pragma unroll
        for (int j = 0; j < 4; j++) acc[i][j] = 0.f;

    for (int k = 0; k < 256; k += 4) {
        float4 a[4];
#pragma unroll
        for (int i = 0; i < 4; i++) a[i] = *(float4*)&xs[(tr * 4 + i) * 256 + k];
#pragma unroll
        for (int kk = 0; kk < 4; kk++) {
            float4 b = *(float4*)&Ws[(k + kk) * 128 + tc * 4];
#pragma unroll
            for (int i = 0; i < 4; i++) {
                float av = ((float*)&a[i])[kk];
                acc[i][0] += av * b.x; acc[i][1] += av * b.y;
                acc[i][2] += av * b.z; acc[i][3] += av * b.w;
            }
        }
    }
    float4 bv = ((const float4*)bias)[tc];
#pragma unroll
    for (int i = 0; i < 4; i++) {
        int r = tr * 4 + i;
        ys[r * 128 + tc * 4 + 0] = acc[i][0] + bv.x;
        ys[r * 128 + tc * 4 + 1] = acc[i][1] + bv.y;
        ys[r * 128 + tc * 4 + 2] = acc[i][2] + bv.z;
        ys[r * 128 + tc * 4 + 3] = acc[i][3] + bv.w;
    }
    __syncthreads();

    const int wid = tid >> 5, lane = tid & 31;
    float4 sc = ((const float4*)lns)[lane];
    float4 of = ((const float4*)lno)[lane];
#pragma unroll
    for (int rr = 0; rr < 4; rr++) {
        int r = wid * 4 + rr;
        float4 v = ((float4*)ys)[r * 32 + lane];
        float s = v.x + v.y + v.z + v.w;
#pragma unroll
        for (int o = 16; o; o >>= 1) s += __shfl_xor_sync(0xffffffffu, s, o);
        float mean = s * (1.0f / 128.0f);
        float dx = v.x - mean, dy = v.y - mean, dz = v.z - mean, dw = v.w - mean;
        float q = dx * dx + dy * dy + dz * dz + dw * dw;
#pragma unroll
        for (int o = 16; o; o >>= 1) q += __shfl_xor_sync(0xffffffffu, q, o);
        float rstd = rsqrtf(q * (1.0f / 128.0f) + 1e-5f);
        int row = row0 + r;
        if (row < N) {
            float4 res = *(float4*)&xs[r * 256 + lane * 4];  // staged n_in
            float4 o4;
            o4.x = res.x + dx * rstd * sc.x + of.x;
            o4.y = res.y + dy * rstd * sc.y + of.y;
            o4.z = res.z + dz * rstd * sc.z + of.z;
            o4.w = res.w + dw * rstd * sc.w + of.w;
            ((float4*)n_out)[(size_t)row * 32 + lane] = o4;
        }
    }
}

// =====================================================================================
extern "C" void kernel_launch(void* const* d_in, const int* in_sizes, int n_in,
                              void* d_out, int out_size)
{
    const float* nodes     = (const float*)d_in[0];
    const float* edges     = (const float*)d_in[1];
    const int*   senders   = (const int*)d_in[2];
    const int*   receivers = (const int*)d_in[3];
    const float* w_node    = (const float*)d_in[4];
    const float* b_node    = (const float*)d_in[5];
    const float* w_edge    = (const float*)d_in[6];
    const float* b_edge    = (const float*)d_in[7];
    const float* ln_n_s    = (const float*)d_in[8];
    const float* ln_n_o    = (const float*)d_in[9];
    const float* ln_e_s    = (const float*)d_in[10];
    const float* ln_e_o    = (const float*)d_in[11];
    const float* msg_w1    = (const float*)d_in[12];
    const float* msg_b1    = (const float*)d_in[13];
    const float* msg_w2    = (const float*)d_in[14];
    const float* msg_b2    = (const float*)d_in[15];
    const float* upd_w     = (const float*)d_in[16];
    const float* upd_b     = (const float*)d_in[17];
    const float* ln_s      = (const float*)d_in[18];
    const float* ln_o      = (const float*)d_in[19];

    const int N = in_sizes[0] / D;
    const int E = in_sizes[1] / D;

    float *pn, *pe, *pPs, *pPr, *pPe, *pagg;
    cudaGetSymbolAddress((void**)&pn,   g_n);
    cudaGetSymbolAddress((void**)&pe,   g_e);
    cudaGetSymbolAddress((void**)&pPs,  g_Ps);
    cudaGetSymbolAddress((void**)&pPr,  g_Pr);
    cudaGetSymbolAddress((void**)&pPe,  g_Pe);
    cudaGetSymbolAddress((void**)&pagg, g_agg);

    const size_t embed_smem = (size_t)(128 * 128 + 32 * 128 + 32 * 128) * 4;          // 96KB
    const size_t gemm_smem  = (size_t)(128 * 256 + 64 * 128) * 4;                     // 160KB
    const size_t msg_smem   = (size_t)(256 * 128 + 64 * 256) * 4 + 64 * 4;            // ~192.25KB
    const size_t upd_smem   = (size_t)(256 * 128 + 32 * 256 + 32 * 128) * 4;          // 176KB

    cudaFuncSetAttribute(embed_kernel,      cudaFuncAttributeMaxDynamicSharedMemorySize, (int)embed_smem);
    cudaFuncSetAttribute(gemm_k128_n256,    cudaFuncAttributeMaxDynamicSharedMemorySize, (int)gemm_smem);
    cudaFuncSetAttribute(edge_msg_kernel,   cudaFuncAttributeMaxDynamicSharedMemorySize, (int)msg_smem);
    cudaFuncSetAttribute(node_update_kernel,cudaFuncAttributeMaxDynamicSharedMemorySize, (int)upd_smem);

    embed_kernel<<<(N + 31) / 32, 256, embed_smem>>>(nodes, w_node, b_node, ln_n_s, ln_n_o, pn, N);
    embed_kernel<<<(E + 31) / 32, 256, embed_smem>>>(edges, w_edge, b_edge, ln_e_s, ln_e_o, pe, E);

    for (int l = 0; l < 3; l++) {
        const float* w1 = msg_w1 + (size_t)l * 384 * 256;
        gemm_k128_n256<<<(N + 63) / 64, 256, gemm_smem>>>(pn, w1,             pPs, N);
        gemm_k128_n256<<<(N + 63) / 64, 256, gemm_smem>>>(pn, w1 + 128 * 256, pPr, N);
        gemm_k128_n256<<<(E + 63) / 64, 256, gemm_smem>>>(pe, w1 + 256 * 256, pPe, E);
        cudaMemsetAsync(pagg, 0, (size_t)N * D * sizeof(float), 0);
        edge_msg_kernel<<<(E + 63) / 64, 256, msg_smem>>>(
            pPs, pPr, pPe, msg_b1 + (size_t)l * 256,
            msg_w2 + (size_t)l * 256 * 128, msg_b2 + (size_t)l * 128,
            senders, receivers, pagg, E);
        float* nout = (l == 2) ? (float*)d_out : pn;
        node_update_kernel<<<(N + 31) / 32, 256, upd_smem>>>(
            pn, pagg, upd_w + (size_t)l * 256 * 128, upd_b + (size_t)l * 128,
            ln_s + (size_t)l * 128, ln_o + (size_t)l * 128, nout, N);
    }
}